// round 15
// baseline (speedup 1.0000x reference)
#include <cuda_runtime.h>
#include <stdint.h>

#define NUM_TOKENS 2048
#define HIDDEN     768
#define MAXW       20
#define NUM_CAND   40960
#define UNARY      1024
#define SPAN_DIM   2324     // 3*768 + 20
#define NTOP       512
#define NPAD       65536
#define NPAIR      65536    // s*32 + w
#define NSEL       32768    // 8 chunks x top 4096

typedef unsigned long long ull;

// ---------------- device scratch ----------------
__device__ float g_P[NUM_TOKENS * 3072];   // [tok][0:1024)=H1a, [1024:2048)=H1b, [2048:3072)=HD
__device__ float g_tok_att[NUM_TOKENS];
__device__ float g_prior[MAXW];
__device__ float g_Cw[MAXW * UNARY];
__device__ float g_pprobs[NPAIR * MAXW];
__device__ float g_pair_score[NPAIR];
__device__ int   g_pair_mark[NPAIR];
__device__ ull   g_keys[NPAD];
__device__ ull   g_keys2[NSEL];
__device__ float g_scores[NUM_CAND];
__device__ int   g_sorted_se[NSEL];
__device__ int   g_pidx[NTOP];
__device__ int   g_hist[NUM_TOKENS];
__device__ int   g_base[NUM_TOKENS];
__device__ int   g_perm[NUM_CAND];

// ---------------- f32x2 packed helpers ----------------
__device__ __forceinline__ ull pack2(float lo, float hi) {
    ull r; asm("mov.b64 %0, {%1, %2};" : "=l"(r) : "f"(lo), "f"(hi)); return r;
}
__device__ __forceinline__ ull fma2(ull a, ull b, ull c) {
    ull d; asm("fma.rn.f32x2 %0, %1, %2, %3;" : "=l"(d) : "l"(a), "l"(b), "l"(c)); return d;
}
__device__ __forceinline__ float2 unpack2(ull v) {
    float2 f; asm("mov.b64 {%0, %1}, %2;" : "=f"(f.x), "=f"(f.y) : "l"(v)); return f;
}

// ---------------- combined zero: hist, key padding, pair marks ----------------
__global__ void zero_kernel() {
    int i = blockIdx.x * 256 + threadIdx.x;        // 256*256 = 65536
    if (i < NUM_TOKENS) g_hist[i] = 0;
    if (i < NPAD - NUM_CAND) g_keys[NUM_CAND + i] = ~0ull;
    g_pair_mark[i] = 0;
}

// ---------------- presence + start histogram ----------------
__global__ void presence_kernel(const int* __restrict__ starts,
                                const int* __restrict__ ends) {
    int c = blockIdx.x * 256 + threadIdx.x;
    if (c < NUM_CAND) {
        int s = starts[c];
        g_pair_mark[(s << 5) | (ends[c] - s)] = 1;
        atomicAdd(&g_hist[s], 1);
    }
}

// ---------------- tok_att = hidden @ w_attn + b_attn ----------------
__global__ void tok_att_kernel(const float* __restrict__ hid,
                               const float* __restrict__ w,
                               const float* __restrict__ b) {
    int warp = (blockIdx.x * blockDim.x + threadIdx.x) >> 5;
    int lane = threadIdx.x & 31;
    if (warp >= NUM_TOKENS) return;
    float acc = 0.f;
    for (int k = lane; k < HIDDEN; k += 32)
        acc += hid[(size_t)warp * HIDDEN + k] * w[k];
    #pragma unroll
    for (int o = 16; o; o >>= 1) acc += __shfl_down_sync(0xffffffffu, acc, o);
    if (lane == 0) g_tok_att[warp] = acc + b[0];
}

// ---------------- width tables ----------------
__global__ void tables_kernel(const float* __restrict__ ew,
                              const float* __restrict__ ewp,
                              const float* __restrict__ W1,
                              const float* __restrict__ Wp1,
                              const float* __restrict__ bp1,
                              const float* __restrict__ Wp2,
                              const float* __restrict__ bp2) {
    int w = blockIdx.x;
    int tid = threadIdx.x;
    __shared__ float red[256];
    float local = 0.f;
    for (int u = tid; u < UNARY; u += 256) {
        float cw = 0.f, hp = 0.f;
        #pragma unroll
        for (int f = 0; f < MAXW; f++) {
            cw += ew [w * MAXW + f] * W1 [(size_t)(1536 + f) * UNARY + u];
            hp += ewp[w * MAXW + f] * Wp1[(size_t)f * UNARY + u];
        }
        g_Cw[w * UNARY + u] = cw;
        hp += bp1[u];
        hp = fmaxf(hp, 0.f);
        local += hp * Wp2[u];
    }
    red[tid] = local;
    __syncthreads();
    for (int s = 128; s; s >>= 1) {
        if (tid < s) red[tid] += red[tid + s];
        __syncthreads();
    }
    if (tid == 0) g_prior[w] = red[0] + bp2[0];
}

// ---------------- counting-sort permutation by start ----------------
__global__ __launch_bounds__(1024) void scan_kernel() {
    __shared__ int a[2048], b[2048];
    int t = threadIdx.x;
    a[t] = g_hist[t]; a[t + 1024] = g_hist[t + 1024];
    __syncthreads();
    int* src = a; int* dst = b;
    for (int off = 1; off < 2048; off <<= 1) {
        #pragma unroll
        for (int q = 0; q < 2; q++) {
            int i = t + q * 1024;
            dst[i] = src[i] + (i >= off ? src[i - off] : 0);
        }
        __syncthreads();
        int* tmp = src; src = dst; dst = tmp;
    }
    g_base[t]        = t ? src[t - 1] : 0;
    g_base[t + 1024] = src[t + 1023];
}
__global__ void scatter_kernel(const int* __restrict__ starts) {
    int c = blockIdx.x * 256 + threadIdx.x;
    if (c < NUM_CAND) {
        int pos = atomicAdd(&g_base[starts[c]], 1);
        g_perm[pos] = c;
    }
}

// ---------------- SGEMM half (R8 quadrant tile, conflict-free LDS, f32x2) ----------------
#define BM 128
#define BN 128
#define BK 16
__global__ __launch_bounds__(256, 2) void sgemm_kernel(const float* __restrict__ A,
                                                       const float* __restrict__ W1,
                                                       int m0) {
    __shared__ float As[2][BK][BM];
    __shared__ float Bs[2][BK][BN];
    int bm = m0 + blockIdx.y * BM, bn = blockIdx.x * BN;
    int tid = threadIdx.x;
    int tr = tid >> 4, tc = tid & 15;

    ull acc[2][4][4];
    #pragma unroll
    for (int q = 0; q < 2; q++)
        #pragma unroll
        for (int i = 0; i < 4; i++)
            #pragma unroll
            for (int p = 0; p < 4; p++) acc[q][i][p] = 0ull;

    int a_row = tid >> 2;
    int a_col = (tid & 3) << 2;
    int b_k   = tid >> 5;
    int b_n   = (tid & 31) << 2;

    int n_global = bn + b_n;
    int seg_off = (n_global < 1024) ? 0 : (n_global < 2048 ? 768 : 1556);
    int col = n_global & 1023;

    float4 ra0, ra1, rb0, rb1;
    ra0 = *reinterpret_cast<const float4*>(&A[(size_t)(bm + a_row) * HIDDEN + a_col]);
    ra1 = *reinterpret_cast<const float4*>(&A[(size_t)(bm + a_row + 64) * HIDDEN + a_col]);
    rb0 = *reinterpret_cast<const float4*>(&W1[(size_t)(seg_off + b_k) * UNARY + col]);
    rb1 = *reinterpret_cast<const float4*>(&W1[(size_t)(seg_off + b_k + 8) * UNARY + col]);
    {
        As[0][a_col + 0][a_row] = ra0.x; As[0][a_col + 1][a_row] = ra0.y;
        As[0][a_col + 2][a_row] = ra0.z; As[0][a_col + 3][a_row] = ra0.w;
        As[0][a_col + 0][a_row + 64] = ra1.x; As[0][a_col + 1][a_row + 64] = ra1.y;
        As[0][a_col + 2][a_row + 64] = ra1.z; As[0][a_col + 3][a_row + 64] = ra1.w;
        *reinterpret_cast<float4*>(&Bs[0][b_k][b_n]) = rb0;
        *reinterpret_cast<float4*>(&Bs[0][b_k + 8][b_n]) = rb1;
    }
    __syncthreads();

    int buf = 0;
    for (int kt = 0; kt < HIDDEN; kt += BK) {
        bool more = (kt + BK) < HIDDEN;
        if (more) {
            int kn = kt + BK;
            ra0 = *reinterpret_cast<const float4*>(&A[(size_t)(bm + a_row) * HIDDEN + kn + a_col]);
            ra1 = *reinterpret_cast<const float4*>(&A[(size_t)(bm + a_row + 64) * HIDDEN + kn + a_col]);
            rb0 = *reinterpret_cast<const float4*>(&W1[(size_t)(seg_off + kn + b_k) * UNARY + col]);
            rb1 = *reinterpret_cast<const float4*>(&W1[(size_t)(seg_off + kn + b_k + 8) * UNARY + col]);
        }
        #pragma unroll
        for (int kk = 0; kk < BK; kk++) {
            float4 a0 = *reinterpret_cast<const float4*>(&As[buf][kk][tr * 4]);
            float4 a1 = *reinterpret_cast<const float4*>(&As[buf][kk][64 + tr * 4]);
            ulonglong2 b0 = *reinterpret_cast<const ulonglong2*>(&Bs[buf][kk][tc * 4]);
            ulonglong2 b1v = *reinterpret_cast<const ulonglong2*>(&Bs[buf][kk][64 + tc * 4]);
            ull ap[8];
            ap[0] = pack2(a0.x, a0.x); ap[1] = pack2(a0.y, a0.y);
            ap[2] = pack2(a0.z, a0.z); ap[3] = pack2(a0.w, a0.w);
            ap[4] = pack2(a1.x, a1.x); ap[5] = pack2(a1.y, a1.y);
            ap[6] = pack2(a1.z, a1.z); ap[7] = pack2(a1.w, a1.w);
            #pragma unroll
            for (int q = 0; q < 2; q++)
                #pragma unroll
                for (int i = 0; i < 4; i++) {
                    ull aa = ap[q * 4 + i];
                    acc[q][i][0] = fma2(aa, b0.x,  acc[q][i][0]);
                    acc[q][i][1] = fma2(aa, b0.y,  acc[q][i][1]);
                    acc[q][i][2] = fma2(aa, b1v.x, acc[q][i][2]);
                    acc[q][i][3] = fma2(aa, b1v.y, acc[q][i][3]);
                }
        }
        if (more) {
            int nb = buf ^ 1;
            As[nb][a_col + 0][a_row] = ra0.x; As[nb][a_col + 1][a_row] = ra0.y;
            As[nb][a_col + 2][a_row] = ra0.z; As[nb][a_col + 3][a_row] = ra0.w;
            As[nb][a_col + 0][a_row + 64] = ra1.x; As[nb][a_col + 1][a_row + 64] = ra1.y;
            As[nb][a_col + 2][a_row + 64] = ra1.z; As[nb][a_col + 3][a_row + 64] = ra1.w;
            *reinterpret_cast<float4*>(&Bs[nb][b_k][b_n]) = rb0;
            *reinterpret_cast<float4*>(&Bs[nb][b_k + 8][b_n]) = rb1;
            __syncthreads();
            buf = nb;
        }
    }
    #pragma unroll
    for (int q = 0; q < 2; q++)
        #pragma unroll
        for (int i = 0; i < 4; i++) {
            int row = bm + q * 64 + tr * 4 + i;
            float2 v0 = unpack2(acc[q][i][0]), v1 = unpack2(acc[q][i][1]);
            float2 v2 = unpack2(acc[q][i][2]), v3 = unpack2(acc[q][i][3]);
            float4 w0 = make_float4(v0.x, v0.y, v1.x, v1.y);
            float4 w1 = make_float4(v2.x, v2.y, v3.x, v3.y);
            *reinterpret_cast<float4*>(&g_P[(size_t)row * 3072 + bn + tc * 4])      = w0;
            *reinterpret_cast<float4*>(&g_P[(size_t)row * 3072 + bn + 64 + tc * 4]) = w1;
        }
}

// ---------------- softmax probs: one warp per PRESENT pair (sparse, ordered) ----------------
__global__ __launch_bounds__(256) void p_pair_kernel() {
    int pid = blockIdx.x * 8 + (threadIdx.x >> 5);
    int lane = threadIdx.x & 31;
    if (pid >= NPAIR) return;
    if (!g_pair_mark[pid]) return;
    int s = pid >> 5, wi = pid & 31;
    float l = (lane <= wi) ? g_tok_att[s + lane] : __int_as_float(0xff800000);
    float m = l;
    #pragma unroll
    for (int o = 16; o; o >>= 1) m = fmaxf(m, __shfl_xor_sync(0xffffffffu, m, o));
    float ex = (lane <= wi) ? expf(l - m) : 0.f;
    float sm = ex;
    #pragma unroll
    for (int o = 16; o; o >>= 1) sm += __shfl_xor_sync(0xffffffffu, sm, o);
    if (lane < MAXW) g_pprobs[pid * MAXW + lane] = (lane <= wi) ? (ex / sm) : 0.f;
}

// ---------------- span_emb rows (perm order, streaming stores) ----------------
__global__ __launch_bounds__(192) void emb_kernel(const float* __restrict__ hid,
                                                  const int* __restrict__ starts,
                                                  const int* __restrict__ ends,
                                                  const float* __restrict__ ew,
                                                  float* __restrict__ out) {
    int c = g_perm[blockIdx.x];
    int tid = threadIdx.x;
    int s = starts[c], e = ends[c];
    int wi = e - s;
    int pid = (s << 5) | wi;

    __shared__ float p[MAXW];
    if (tid < MAXW) p[tid] = g_pprobs[pid * MAXW + tid];
    __syncthreads();

    float4* row4 = reinterpret_cast<float4*>(out + (size_t)c * SPAN_DIM);
    const float4* hid4 = reinterpret_cast<const float4*>(hid);

    float4 acc = make_float4(0.f, 0.f, 0.f, 0.f);
    for (int i = 0; i <= wi; i++) {
        float4 v = hid4[(size_t)(s + i) * 192 + tid];
        if (i == 0)  __stcs(&row4[tid], v);
        if (i == wi) __stcs(&row4[192 + tid], v);
        float pi = p[i];
        acc.x += pi * v.x; acc.y += pi * v.y; acc.z += pi * v.z; acc.w += pi * v.w;
    }
    __stcs(&row4[389 + tid], acc);
    if (tid < 5) {
        float4 w = reinterpret_cast<const float4*>(ew)[wi * 5 + tid];
        __stcs(&row4[384 + tid], w);
    }
}

// ---------------- score: one warp per PRESENT pair (sparse, ordered) ----------------
__global__ __launch_bounds__(256) void score_pair_kernel(const float* __restrict__ b1,
                                                         const float* __restrict__ W2,
                                                         const float* __restrict__ b2v) {
    int pid = blockIdx.x * 8 + (threadIdx.x >> 5);
    int lane = threadIdx.x & 31;
    if (pid >= NPAIR) return;
    if (!g_pair_mark[pid]) return;
    int s = pid >> 5, wi = pid & 31;
    int e = s + wi;

    float pv = (lane <= wi) ? g_pprobs[pid * MAXW + lane] : 0.f;

    const float4* pa  = reinterpret_cast<const float4*>(&g_P[(size_t)s * 3072]);
    const float4* pb  = reinterpret_cast<const float4*>(&g_P[(size_t)e * 3072 + 1024]);
    const float4* pcw = reinterpret_cast<const float4*>(&g_Cw[wi * UNARY]);
    const float4* pb1 = reinterpret_cast<const float4*>(b1);

    float4 acc[8];
    #pragma unroll
    for (int j = 0; j < 8; j++) {
        int idx = j * 32 + lane;
        float4 a = pa[idx], b = pb[idx], cw = pcw[idx], bb = pb1[idx];
        acc[j].x = a.x + b.x + cw.x + bb.x;
        acc[j].y = a.y + b.y + cw.y + bb.y;
        acc[j].z = a.z + b.z + cw.z + bb.z;
        acc[j].w = a.w + b.w + cw.w + bb.w;
    }
    for (int i = 0; i <= wi; i++) {
        float pi = __shfl_sync(0xffffffffu, pv, i);
        const float4* hd = reinterpret_cast<const float4*>(&g_P[(size_t)(s + i) * 3072 + 2048]);
        #pragma unroll
        for (int j = 0; j < 8; j++) {
            float4 v = hd[j * 32 + lane];
            acc[j].x += pi * v.x; acc[j].y += pi * v.y;
            acc[j].z += pi * v.z; acc[j].w += pi * v.w;
        }
    }
    const float4* W2_4 = reinterpret_cast<const float4*>(W2);
    float local = 0.f;
    #pragma unroll
    for (int j = 0; j < 8; j++) {
        float4 w = W2_4[j * 32 + lane];
        local += fmaxf(acc[j].x, 0.f) * w.x + fmaxf(acc[j].y, 0.f) * w.y
               + fmaxf(acc[j].z, 0.f) * w.z + fmaxf(acc[j].w, 0.f) * w.w;
    }
    #pragma unroll
    for (int o = 16; o; o >>= 1) local += __shfl_xor_sync(0xffffffffu, local, o);
    if (lane == 0) g_pair_score[pid] = local + b2v[0] + g_prior[wi];
}

// ---------------- broadcast pair score to candidates + build keys ----------------
__global__ void broadcast_kernel(const int* __restrict__ starts,
                                 const int* __restrict__ ends) {
    int c = blockIdx.x * 256 + threadIdx.x;
    if (c >= NUM_CAND) return;
    int s = starts[c];
    float sc = g_pair_score[(s << 5) | (ends[c] - s)];
    g_scores[c] = sc;
    unsigned u = __float_as_uint(sc);
    u = (u & 0x80000000u) ? ~u : (u | 0x80000000u);
    g_keys[c] = ((ull)(~u) << 32) | (unsigned)c;
}

// ---------------- stage 1: 8 chunks of 8192, each fully sorted ASCENDING ----------------
#define SORT_SMEM (8192 * 8)
__global__ __launch_bounds__(1024) void bitonic_smem_full8k() {
    extern __shared__ ull sk[];
    int base = blockIdx.x * 8192, t = threadIdx.x;
    #pragma unroll
    for (int r = 0; r < 8; r++) sk[t + r * 1024] = g_keys[base + t + r * 1024];
    __syncthreads();
    for (int k = 2; k <= 8192; k <<= 1)
        for (int j = k >> 1; j > 0; j >>= 1) {
            #pragma unroll
            for (int q = 0; q < 4; q++) {
                int pI = t + q * 1024;
                int i = ((pI & ~(j - 1)) << 1) | (pI & (j - 1));
                bool dir = ((i & k) == 0);    // all chunks ascending
                ull a = sk[i], b = sk[i | j];
                if ((a > b) == dir) { sk[i] = b; sk[i | j] = a; }
            }
            __syncthreads();
        }
    #pragma unroll
    for (int r = 0; r < 8; r++) g_keys[base + t + r * 1024] = sk[t + r * 1024];
}

// ---------------- stage 2: gather per-chunk top 4096 into g_keys2 ----------------
__global__ void gather_top_kernel() {
    int j = blockIdx.x * 256 + threadIdx.x;      // 0..32767
    if (j < NSEL) {
        int chunk = j >> 12, off = j & 4095;
        g_keys2[j] = g_keys[chunk * 8192 + off];
    }
}

// ---------------- stage 3: sort 32768 = 2 x 16384 smem + merge ----------------
#define SORT_SMEM16 (16384 * 8)
__global__ __launch_bounds__(1024) void bitonic_full16k2() {
    extern __shared__ ull sk[];
    int base = blockIdx.x * 16384, t = threadIdx.x;
    #pragma unroll
    for (int r = 0; r < 16; r++) sk[t + r * 1024] = g_keys2[base + t + r * 1024];
    __syncthreads();
    for (int k = 2; k <= 16384; k <<= 1)
        for (int j = k >> 1; j > 0; j >>= 1) {
            #pragma unroll
            for (int q = 0; q < 8; q++) {
                int pI = t + q * 1024;
                int i = ((pI & ~(j - 1)) << 1) | (pI & (j - 1));
                bool dir = (((base + i) & k) == 0);
                ull a = sk[i], b = sk[i | j];
                if ((a > b) == dir) { sk[i] = b; sk[i | j] = a; }
            }
            __syncthreads();
        }
    #pragma unroll
    for (int r = 0; r < 16; r++) g_keys2[base + t + r * 1024] = sk[t + r * 1024];
}

__global__ void gstep2(int j, int k) {
    int pI = blockIdx.x * blockDim.x + threadIdx.x;   // NSEL/2 = 16384 pairs
    int i = ((pI & ~(j - 1)) << 1) | (pI & (j - 1));
    bool dir = ((i & k) == 0);
    ull a = g_keys2[i], b = g_keys2[i | j];
    if ((a > b) == dir) { g_keys2[i] = b; g_keys2[i | j] = a; }
}

// tail j=8192..1 within 16384 chunks, k=32768; fuses decorate
__global__ __launch_bounds__(1024) void bitonic_tail16k2(const int* __restrict__ starts,
                                                         const int* __restrict__ ends) {
    extern __shared__ ull sk[];
    const int k = 32768;
    int base = blockIdx.x * 16384, t = threadIdx.x;
    #pragma unroll
    for (int r = 0; r < 16; r++) sk[t + r * 1024] = g_keys2[base + t + r * 1024];
    __syncthreads();
    for (int j = 8192; j > 0; j >>= 1) {
        #pragma unroll
        for (int q = 0; q < 8; q++) {
            int pI = t + q * 1024;
            int i = ((pI & ~(j - 1)) << 1) | (pI & (j - 1));
            bool dir = (((base + i) & k) == 0);
            ull a = sk[i], b = sk[i | j];
            if ((a > b) == dir) { sk[i] = b; sk[i | j] = a; }
        }
        __syncthreads();
    }
    #pragma unroll
    for (int r = 0; r < 16; r++) {
        int li = t + r * 1024;
        ull key = sk[li];
        g_keys2[base + li] = key;
        int idx = (int)(key & 0xffffffffull);
        g_sorted_se[base + li] = (starts[idx] << 16) | ends[idx];
    }
}

// ---------------- serial greedy NMS over top-32768 ----------------
__global__ __launch_bounds__(256) void nms_kernel(const int* __restrict__ starts,
                                                  const int* __restrict__ ends,
                                                  const int* __restrict__ spk,
                                                  float* __restrict__ out) {
    __shared__ int latest[NUM_TOKENS];
    __shared__ int earliest[NUM_TOKENS];
    __shared__ int chunk[2048];
    __shared__ ull akey[NTOP];
    __shared__ int aidx[NTOP];
    __shared__ int s_count;

    int tid = threadIdx.x, lane = tid & 31;
    for (int t = tid; t < NUM_TOKENS; t += 256) { latest[t] = -1; earliest[t] = NUM_TOKENS; }
    if (tid == 0) s_count = 0;
    __syncthreads();

    int count = 0, pos = 0;
    while (pos < NSEL && count < NTOP) {
        int n = min(2048, NSEL - pos);
        for (int t = tid; t < n; t += 256) chunk[t] = g_sorted_se[pos + t];
        __syncthreads();
        if (tid < 32) {
            for (int cI = 0; cI < n && count < NTOP; cI++) {
                int se = chunk[cI];
                int s = se >> 16, e = se & 0xffff;
                int t = s + lane;
                bool act = (lane <= e - s);
                bool c1 = act && (t > s) && (latest[t] > e);
                bool c2 = act && (t < e) && (earliest[t] < s);
                if (__ballot_sync(0xffffffffu, c1 || c2) == 0u) {
                    if (lane == 0) {
                        latest[s] = max(latest[s], e);
                        earliest[e] = min(earliest[e], s);
                        int idx = (int)(g_keys2[pos + cI] & 0xffffffffull);
                        aidx[count] = idx;
                        akey[count] = (((ull)(s * (NUM_TOKENS + 1) + e)) << 10) | (unsigned)count;
                    }
                    count++;
                }
                __syncwarp();
            }
            if (lane == 0) s_count = count;
        }
        __syncthreads();
        count = s_count;
        pos += n;
    }
    __syncthreads();
    for (int r = tid; r < NTOP; r += 256)
        if (r >= count) { akey[r] = ~0ull; aidx[r] = 0; }
    __syncthreads();

    for (int k = 2; k <= NTOP; k <<= 1)
        for (int j = k >> 1; j > 0; j >>= 1) {
            int i = ((tid & ~(j - 1)) << 1) | (tid & (j - 1));
            bool dir = ((i & k) == 0);
            ull a = akey[i], b = akey[i | j];
            if ((a > b) == dir) {
                akey[i] = b; akey[i | j] = a;
                int x = aidx[i]; aidx[i] = aidx[i | j]; aidx[i | j] = x;
            }
            __syncthreads();
        }

    int first = aidx[0];
    const size_t base = (size_t)NUM_CAND * SPAN_DIM;
    const size_t emb_off = base + 3 * NTOP;
    const size_t sc_off = emb_off + (size_t)NTOP * SPAN_DIM;
    for (int r = tid; r < NTOP; r += 256) {
        int idx = (r < count) ? aidx[r] : first;
        int s = starts[idx], e = ends[idx];
        out[base + r]            = (float)idx;
        out[base + NTOP + r]     = (float)s;
        out[base + 2 * NTOP + r] = (float)e;
        out[sc_off + r]          = g_scores[idx];
        out[sc_off + NTOP + r]   = (float)spk[s];
        g_pidx[r] = idx;
    }
}

__global__ void gather_emb(float* __restrict__ out) {
    int r = blockIdx.x;
    int idx = g_pidx[r];
    const float* src = out + (size_t)idx * SPAN_DIM;
    float* dst = out + (size_t)NUM_CAND * SPAN_DIM + 3 * NTOP + (size_t)r * SPAN_DIM;
    for (int d = threadIdx.x; d < SPAN_DIM; d += 256) dst[d] = src[d];
}

// ---------------- launch (multi-stream, graph-capturable fork/join) ----------------
extern "C" void kernel_launch(void* const* d_in, const int* in_sizes, int n_in,
                              void* d_out, int out_size) {
    const float* hid    = (const float*)d_in[0];
    const int*   starts = (const int*)  d_in[1];
    const int*   ends   = (const int*)  d_in[2];
    const int*   spk    = (const int*)  d_in[3];
    const float* w_attn = (const float*)d_in[4];
    const float* b_attn = (const float*)d_in[5];
    const float* W1     = (const float*)d_in[6];
    const float* b1     = (const float*)d_in[7];
    const float* W2     = (const float*)d_in[8];
    const float* b2     = (const float*)d_in[9];
    const float* ew     = (const float*)d_in[10];
    const float* ewp    = (const float*)d_in[11];
    const float* Wp1    = (const float*)d_in[12];
    const float* bp1    = (const float*)d_in[13];
    const float* Wp2    = (const float*)d_in[14];
    const float* bp2    = (const float*)d_in[15];
    float* out = (float*)d_out;

    static cudaStream_t sB = 0, sC = 0, sD = 0;
    static cudaEvent_t evRoot = 0, evGL = 0, evGH = 0, evP = 0, evEmb = 0,
                       evScore = 0, evZero = 0;
    if (!sB) {
        cudaStreamCreateWithFlags(&sB, cudaStreamNonBlocking);
        cudaStreamCreateWithFlags(&sC, cudaStreamNonBlocking);
        cudaStreamCreateWithFlags(&sD, cudaStreamNonBlocking);
        cudaEventCreateWithFlags(&evRoot,  cudaEventDisableTiming);
        cudaEventCreateWithFlags(&evGL,    cudaEventDisableTiming);
        cudaEventCreateWithFlags(&evGH,    cudaEventDisableTiming);
        cudaEventCreateWithFlags(&evP,     cudaEventDisableTiming);
        cudaEventCreateWithFlags(&evEmb,   cudaEventDisableTiming);
        cudaEventCreateWithFlags(&evScore, cudaEventDisableTiming);
        cudaEventCreateWithFlags(&evZero,  cudaEventDisableTiming);
        cudaFuncSetAttribute(bitonic_smem_full8k,
                             cudaFuncAttributeMaxDynamicSharedMemorySize, SORT_SMEM);
        cudaFuncSetAttribute(bitonic_full16k2,
                             cudaFuncAttributeMaxDynamicSharedMemorySize, SORT_SMEM16);
        cudaFuncSetAttribute(bitonic_tail16k2,
                             cudaFuncAttributeMaxDynamicSharedMemorySize, SORT_SMEM16);
    }

    cudaEventRecord(evRoot, 0);
    cudaStreamWaitEvent(sB, evRoot, 0);
    cudaStreamWaitEvent(sC, evRoot, 0);
    cudaStreamWaitEvent(sD, evRoot, 0);

    // GEMM halves CONCURRENT on two streams
    sgemm_kernel<<<dim3(24, 8), 256>>>(hid, W1, 0);             // default stream
    cudaEventRecord(evGL, 0);
    sgemm_kernel<<<dim3(24, 8), 256, 0, sD>>>(hid, W1, 1024);   // sD, concurrent
    cudaEventRecord(evGH, sD);

    // setup chain on sB: zero -> presence -> tok_att -> p_pair -> perm -> emb
    zero_kernel<<<256, 256, 0, sB>>>();
    cudaEventRecord(evZero, sB);
    presence_kernel<<<160, 256, 0, sB>>>(starts, ends);
    tok_att_kernel<<<256, 256, 0, sB>>>(hid, w_attn, b_attn);
    p_pair_kernel<<<NPAIR / 8, 256, 0, sB>>>();
    cudaEventRecord(evP, sB);
    scan_kernel<<<1, 1024, 0, sB>>>();
    scatter_kernel<<<160, 256, 0, sB>>>(starts);
    emb_kernel<<<NUM_CAND, 192, 0, sB>>>(hid, starts, ends, ew, out);
    cudaEventRecord(evEmb, sB);

    // tables + score on sC
    tables_kernel<<<20, 256, 0, sC>>>(ew, ewp, W1, Wp1, bp1, Wp2, bp2);
    cudaStreamWaitEvent(sC, evP, 0);
    cudaStreamWaitEvent(sC, evGL, 0);
    cudaStreamWaitEvent(sC, evGH, 0);
    score_pair_kernel<<<NPAIR / 8, 256, 0, sC>>>(b1, W2, b2);
    broadcast_kernel<<<160, 256, 0, sC>>>(starts, ends);
    cudaEventRecord(evScore, sC);

    // join on default stream: chunk-sort -> gather-top -> merge-sort(+decorate) -> nms -> gather
    cudaStreamWaitEvent(0, evScore, 0);
    cudaStreamWaitEvent(0, evZero, 0);
    bitonic_smem_full8k<<<8, 1024, SORT_SMEM>>>();
    gather_top_kernel<<<128, 256>>>();
    bitonic_full16k2<<<2, 1024, SORT_SMEM16>>>();
    gstep2<<<64, 256>>>(16384, 32768);
    bitonic_tail16k2<<<2, 1024, SORT_SMEM16>>>(starts, ends);
    nms_kernel<<<1, 256>>>(starts, ends, spk, out);
    cudaStreamWaitEvent(0, evEmb, 0);
    gather_emb<<<NTOP, 256>>>(out);
}

// round 16
// speedup vs baseline: 1.2175x; 1.2175x over previous
#include <cuda_runtime.h>
#include <stdint.h>

#define NUM_TOKENS 2048
#define HIDDEN     768
#define MAXW       20
#define NUM_CAND   40960
#define UNARY      1024
#define SPAN_DIM   2324     // 3*768 + 20
#define NTOP       512
#define NPAD       65536
#define NPAIR      65536    // s*32 + w

typedef unsigned long long ull;

// ---------------- device scratch ----------------
__device__ float g_P[NUM_TOKENS * 3072];   // [tok][0:1024)=H1a, [1024:2048)=H1b, [2048:3072)=HD
__device__ float g_tok_att[NUM_TOKENS];
__device__ float g_prior[MAXW];
__device__ float g_Cw[MAXW * UNARY];
__device__ float g_pprobs[NPAIR * MAXW];
__device__ float g_pair_score[NPAIR];
__device__ int   g_pair_mark[NPAIR];
__device__ ull   g_keys[NPAD];
__device__ float g_scores[NUM_CAND];
__device__ int   g_sorted_se[NUM_CAND];
__device__ int   g_pidx[NTOP];
__device__ int   g_hist[NUM_TOKENS];
__device__ int   g_base[NUM_TOKENS];
__device__ int   g_perm[NUM_CAND];

// ---------------- f32x2 packed helpers ----------------
__device__ __forceinline__ ull pack2(float lo, float hi) {
    ull r; asm("mov.b64 %0, {%1, %2};" : "=l"(r) : "f"(lo), "f"(hi)); return r;
}
__device__ __forceinline__ ull fma2(ull a, ull b, ull c) {
    ull d; asm("fma.rn.f32x2 %0, %1, %2, %3;" : "=l"(d) : "l"(a), "l"(b), "l"(c)); return d;
}
__device__ __forceinline__ float2 unpack2(ull v) {
    float2 f; asm("mov.b64 {%0, %1}, %2;" : "=f"(f.x), "=f"(f.y) : "l"(v)); return f;
}

// ---------------- combined zero: hist, key padding, pair marks ----------------
__global__ void zero_kernel() {
    int i = blockIdx.x * 256 + threadIdx.x;        // 256*256 = 65536
    if (i < NUM_TOKENS) g_hist[i] = 0;
    if (i < NPAD - NUM_CAND) g_keys[NUM_CAND + i] = ~0ull;
    g_pair_mark[i] = 0;
}

// ---------------- presence + start histogram ----------------
__global__ void presence_kernel(const int* __restrict__ starts,
                                const int* __restrict__ ends) {
    int c = blockIdx.x * 256 + threadIdx.x;
    if (c < NUM_CAND) {
        int s = starts[c];
        g_pair_mark[(s << 5) | (ends[c] - s)] = 1;
        atomicAdd(&g_hist[s], 1);
    }
}

// ---------------- tok_att = hidden @ w_attn + b_attn ----------------
__global__ void tok_att_kernel(const float* __restrict__ hid,
                               const float* __restrict__ w,
                               const float* __restrict__ b) {
    int warp = (blockIdx.x * blockDim.x + threadIdx.x) >> 5;
    int lane = threadIdx.x & 31;
    if (warp >= NUM_TOKENS) return;
    float acc = 0.f;
    for (int k = lane; k < HIDDEN; k += 32)
        acc += hid[(size_t)warp * HIDDEN + k] * w[k];
    #pragma unroll
    for (int o = 16; o; o >>= 1) acc += __shfl_down_sync(0xffffffffu, acc, o);
    if (lane == 0) g_tok_att[warp] = acc + b[0];
}

// ---------------- width tables ----------------
__global__ void tables_kernel(const float* __restrict__ ew,
                              const float* __restrict__ ewp,
                              const float* __restrict__ W1,
                              const float* __restrict__ Wp1,
                              const float* __restrict__ bp1,
                              const float* __restrict__ Wp2,
                              const float* __restrict__ bp2) {
    int w = blockIdx.x;
    int tid = threadIdx.x;
    __shared__ float red[256];
    float local = 0.f;
    for (int u = tid; u < UNARY; u += 256) {
        float cw = 0.f, hp = 0.f;
        #pragma unroll
        for (int f = 0; f < MAXW; f++) {
            cw += ew [w * MAXW + f] * W1 [(size_t)(1536 + f) * UNARY + u];
            hp += ewp[w * MAXW + f] * Wp1[(size_t)f * UNARY + u];
        }
        g_Cw[w * UNARY + u] = cw;
        hp += bp1[u];
        hp = fmaxf(hp, 0.f);
        local += hp * Wp2[u];
    }
    red[tid] = local;
    __syncthreads();
    for (int s = 128; s; s >>= 1) {
        if (tid < s) red[tid] += red[tid + s];
        __syncthreads();
    }
    if (tid == 0) g_prior[w] = red[0] + bp2[0];
}

// ---------------- counting-sort permutation by start ----------------
__global__ __launch_bounds__(1024) void scan_kernel() {
    __shared__ int a[2048], b[2048];
    int t = threadIdx.x;
    a[t] = g_hist[t]; a[t + 1024] = g_hist[t + 1024];
    __syncthreads();
    int* src = a; int* dst = b;
    for (int off = 1; off < 2048; off <<= 1) {
        #pragma unroll
        for (int q = 0; q < 2; q++) {
            int i = t + q * 1024;
            dst[i] = src[i] + (i >= off ? src[i - off] : 0);
        }
        __syncthreads();
        int* tmp = src; src = dst; dst = tmp;
    }
    g_base[t]        = t ? src[t - 1] : 0;
    g_base[t + 1024] = src[t + 1023];
}
__global__ void scatter_kernel(const int* __restrict__ starts) {
    int c = blockIdx.x * 256 + threadIdx.x;
    if (c < NUM_CAND) {
        int pos = atomicAdd(&g_base[starts[c]], 1);
        g_perm[pos] = c;
    }
}

// ---------------- SGEMM half (R8 quadrant tile, conflict-free LDS, f32x2) ----------------
#define BM 128
#define BN 128
#define BK 16
__global__ __launch_bounds__(256, 2) void sgemm_kernel(const float* __restrict__ A,
                                                       const float* __restrict__ W1,
                                                       int m0) {
    __shared__ float As[2][BK][BM];
    __shared__ float Bs[2][BK][BN];
    int bm = m0 + blockIdx.y * BM, bn = blockIdx.x * BN;
    int tid = threadIdx.x;
    int tr = tid >> 4, tc = tid & 15;

    ull acc[2][4][4];
    #pragma unroll
    for (int q = 0; q < 2; q++)
        #pragma unroll
        for (int i = 0; i < 4; i++)
            #pragma unroll
            for (int p = 0; p < 4; p++) acc[q][i][p] = 0ull;

    int a_row = tid >> 2;
    int a_col = (tid & 3) << 2;
    int b_k   = tid >> 5;
    int b_n   = (tid & 31) << 2;

    int n_global = bn + b_n;
    int seg_off = (n_global < 1024) ? 0 : (n_global < 2048 ? 768 : 1556);
    int col = n_global & 1023;

    float4 ra0, ra1, rb0, rb1;
    ra0 = *reinterpret_cast<const float4*>(&A[(size_t)(bm + a_row) * HIDDEN + a_col]);
    ra1 = *reinterpret_cast<const float4*>(&A[(size_t)(bm + a_row + 64) * HIDDEN + a_col]);
    rb0 = *reinterpret_cast<const float4*>(&W1[(size_t)(seg_off + b_k) * UNARY + col]);
    rb1 = *reinterpret_cast<const float4*>(&W1[(size_t)(seg_off + b_k + 8) * UNARY + col]);
    {
        As[0][a_col + 0][a_row] = ra0.x; As[0][a_col + 1][a_row] = ra0.y;
        As[0][a_col + 2][a_row] = ra0.z; As[0][a_col + 3][a_row] = ra0.w;
        As[0][a_col + 0][a_row + 64] = ra1.x; As[0][a_col + 1][a_row + 64] = ra1.y;
        As[0][a_col + 2][a_row + 64] = ra1.z; As[0][a_col + 3][a_row + 64] = ra1.w;
        *reinterpret_cast<float4*>(&Bs[0][b_k][b_n]) = rb0;
        *reinterpret_cast<float4*>(&Bs[0][b_k + 8][b_n]) = rb1;
    }
    __syncthreads();

    int buf = 0;
    for (int kt = 0; kt < HIDDEN; kt += BK) {
        bool more = (kt + BK) < HIDDEN;
        if (more) {
            int kn = kt + BK;
            ra0 = *reinterpret_cast<const float4*>(&A[(size_t)(bm + a_row) * HIDDEN + kn + a_col]);
            ra1 = *reinterpret_cast<const float4*>(&A[(size_t)(bm + a_row + 64) * HIDDEN + kn + a_col]);
            rb0 = *reinterpret_cast<const float4*>(&W1[(size_t)(seg_off + kn + b_k) * UNARY + col]);
            rb1 = *reinterpret_cast<const float4*>(&W1[(size_t)(seg_off + kn + b_k + 8) * UNARY + col]);
        }
        #pragma unroll
        for (int kk = 0; kk < BK; kk++) {
            float4 a0 = *reinterpret_cast<const float4*>(&As[buf][kk][tr * 4]);
            float4 a1 = *reinterpret_cast<const float4*>(&As[buf][kk][64 + tr * 4]);
            ulonglong2 b0 = *reinterpret_cast<const ulonglong2*>(&Bs[buf][kk][tc * 4]);
            ulonglong2 b1v = *reinterpret_cast<const ulonglong2*>(&Bs[buf][kk][64 + tc * 4]);
            ull ap[8];
            ap[0] = pack2(a0.x, a0.x); ap[1] = pack2(a0.y, a0.y);
            ap[2] = pack2(a0.z, a0.z); ap[3] = pack2(a0.w, a0.w);
            ap[4] = pack2(a1.x, a1.x); ap[5] = pack2(a1.y, a1.y);
            ap[6] = pack2(a1.z, a1.z); ap[7] = pack2(a1.w, a1.w);
            #pragma unroll
            for (int q = 0; q < 2; q++)
                #pragma unroll
                for (int i = 0; i < 4; i++) {
                    ull aa = ap[q * 4 + i];
                    acc[q][i][0] = fma2(aa, b0.x,  acc[q][i][0]);
                    acc[q][i][1] = fma2(aa, b0.y,  acc[q][i][1]);
                    acc[q][i][2] = fma2(aa, b1v.x, acc[q][i][2]);
                    acc[q][i][3] = fma2(aa, b1v.y, acc[q][i][3]);
                }
        }
        if (more) {
            int nb = buf ^ 1;
            As[nb][a_col + 0][a_row] = ra0.x; As[nb][a_col + 1][a_row] = ra0.y;
            As[nb][a_col + 2][a_row] = ra0.z; As[nb][a_col + 3][a_row] = ra0.w;
            As[nb][a_col + 0][a_row + 64] = ra1.x; As[nb][a_col + 1][a_row + 64] = ra1.y;
            As[nb][a_col + 2][a_row + 64] = ra1.z; As[nb][a_col + 3][a_row + 64] = ra1.w;
            *reinterpret_cast<float4*>(&Bs[nb][b_k][b_n]) = rb0;
            *reinterpret_cast<float4*>(&Bs[nb][b_k + 8][b_n]) = rb1;
            __syncthreads();
            buf = nb;
        }
    }
    #pragma unroll
    for (int q = 0; q < 2; q++)
        #pragma unroll
        for (int i = 0; i < 4; i++) {
            int row = bm + q * 64 + tr * 4 + i;
            float2 v0 = unpack2(acc[q][i][0]), v1 = unpack2(acc[q][i][1]);
            float2 v2 = unpack2(acc[q][i][2]), v3 = unpack2(acc[q][i][3]);
            float4 w0 = make_float4(v0.x, v0.y, v1.x, v1.y);
            float4 w1 = make_float4(v2.x, v2.y, v3.x, v3.y);
            *reinterpret_cast<float4*>(&g_P[(size_t)row * 3072 + bn + tc * 4])      = w0;
            *reinterpret_cast<float4*>(&g_P[(size_t)row * 3072 + bn + 64 + tc * 4]) = w1;
        }
}

// ---------------- softmax probs: one warp per PRESENT pair (sparse, ordered) ----------------
__global__ __launch_bounds__(256) void p_pair_kernel() {
    int pid = blockIdx.x * 8 + (threadIdx.x >> 5);
    int lane = threadIdx.x & 31;
    if (pid >= NPAIR) return;
    if (!g_pair_mark[pid]) return;
    int s = pid >> 5, wi = pid & 31;
    float l = (lane <= wi) ? g_tok_att[s + lane] : __int_as_float(0xff800000);
    float m = l;
    #pragma unroll
    for (int o = 16; o; o >>= 1) m = fmaxf(m, __shfl_xor_sync(0xffffffffu, m, o));
    float ex = (lane <= wi) ? expf(l - m) : 0.f;
    float sm = ex;
    #pragma unroll
    for (int o = 16; o; o >>= 1) sm += __shfl_xor_sync(0xffffffffu, sm, o);
    if (lane < MAXW) g_pprobs[pid * MAXW + lane] = (lane <= wi) ? (ex / sm) : 0.f;
}

// ---------------- span_emb rows (perm order, streaming stores) ----------------
__global__ __launch_bounds__(192) void emb_kernel(const float* __restrict__ hid,
                                                  const int* __restrict__ starts,
                                                  const int* __restrict__ ends,
                                                  const float* __restrict__ ew,
                                                  float* __restrict__ out) {
    int c = g_perm[blockIdx.x];
    int tid = threadIdx.x;
    int s = starts[c], e = ends[c];
    int wi = e - s;
    int pid = (s << 5) | wi;

    __shared__ float p[MAXW];
    if (tid < MAXW) p[tid] = g_pprobs[pid * MAXW + tid];
    __syncthreads();

    float4* row4 = reinterpret_cast<float4*>(out + (size_t)c * SPAN_DIM);
    const float4* hid4 = reinterpret_cast<const float4*>(hid);

    float4 acc = make_float4(0.f, 0.f, 0.f, 0.f);
    for (int i = 0; i <= wi; i++) {
        float4 v = hid4[(size_t)(s + i) * 192 + tid];
        if (i == 0)  __stcs(&row4[tid], v);
        if (i == wi) __stcs(&row4[192 + tid], v);
        float pi = p[i];
        acc.x += pi * v.x; acc.y += pi * v.y; acc.z += pi * v.z; acc.w += pi * v.w;
    }
    __stcs(&row4[389 + tid], acc);
    if (tid < 5) {
        float4 w = reinterpret_cast<const float4*>(ew)[wi * 5 + tid];
        __stcs(&row4[384 + tid], w);
    }
}

// ---------------- score: one warp per PRESENT pair (sparse, ordered) ----------------
__global__ __launch_bounds__(256) void score_pair_kernel(const float* __restrict__ b1,
                                                         const float* __restrict__ W2,
                                                         const float* __restrict__ b2v) {
    int pid = blockIdx.x * 8 + (threadIdx.x >> 5);
    int lane = threadIdx.x & 31;
    if (pid >= NPAIR) return;
    if (!g_pair_mark[pid]) return;
    int s = pid >> 5, wi = pid & 31;
    int e = s + wi;

    float pv = (lane <= wi) ? g_pprobs[pid * MAXW + lane] : 0.f;

    const float4* pa  = reinterpret_cast<const float4*>(&g_P[(size_t)s * 3072]);
    const float4* pb  = reinterpret_cast<const float4*>(&g_P[(size_t)e * 3072 + 1024]);
    const float4* pcw = reinterpret_cast<const float4*>(&g_Cw[wi * UNARY]);
    const float4* pb1 = reinterpret_cast<const float4*>(b1);

    float4 acc[8];
    #pragma unroll
    for (int j = 0; j < 8; j++) {
        int idx = j * 32 + lane;
        float4 a = pa[idx], b = pb[idx], cw = pcw[idx], bb = pb1[idx];
        acc[j].x = a.x + b.x + cw.x + bb.x;
        acc[j].y = a.y + b.y + cw.y + bb.y;
        acc[j].z = a.z + b.z + cw.z + bb.z;
        acc[j].w = a.w + b.w + cw.w + bb.w;
    }
    for (int i = 0; i <= wi; i++) {
        float pi = __shfl_sync(0xffffffffu, pv, i);
        const float4* hd = reinterpret_cast<const float4*>(&g_P[(size_t)(s + i) * 3072 + 2048]);
        #pragma unroll
        for (int j = 0; j < 8; j++) {
            float4 v = hd[j * 32 + lane];
            acc[j].x += pi * v.x; acc[j].y += pi * v.y;
            acc[j].z += pi * v.z; acc[j].w += pi * v.w;
        }
    }
    const float4* W2_4 = reinterpret_cast<const float4*>(W2);
    float local = 0.f;
    #pragma unroll
    for (int j = 0; j < 8; j++) {
        float4 w = W2_4[j * 32 + lane];
        local += fmaxf(acc[j].x, 0.f) * w.x + fmaxf(acc[j].y, 0.f) * w.y
               + fmaxf(acc[j].z, 0.f) * w.z + fmaxf(acc[j].w, 0.f) * w.w;
    }
    #pragma unroll
    for (int o = 16; o; o >>= 1) local += __shfl_xor_sync(0xffffffffu, local, o);
    if (lane == 0) g_pair_score[pid] = local + b2v[0] + g_prior[wi];
}

// ---------------- broadcast pair score to candidates + build keys ----------------
__global__ void broadcast_kernel(const int* __restrict__ starts,
                                 const int* __restrict__ ends) {
    int c = blockIdx.x * 256 + threadIdx.x;
    if (c >= NUM_CAND) return;
    int s = starts[c];
    float sc = g_pair_score[(s << 5) | (ends[c] - s)];
    g_scores[c] = sc;
    unsigned u = __float_as_uint(sc);
    u = (u & 0x80000000u) ? ~u : (u | 0x80000000u);
    g_keys[c] = ((ull)(~u) << 32) | (unsigned)c;
}

// ---------------- bitonic sort, 8192-element smem chunks (R12 proven) ----------------
#define SORT_SMEM (8192 * 8)
__global__ __launch_bounds__(1024) void bitonic_smem_full8k() {
    extern __shared__ ull sk[];
    int base = blockIdx.x * 8192, t = threadIdx.x;
    #pragma unroll
    for (int r = 0; r < 8; r++) sk[t + r * 1024] = g_keys[base + t + r * 1024];
    __syncthreads();
    for (int k = 2; k <= 8192; k <<= 1)
        for (int j = k >> 1; j > 0; j >>= 1) {
            #pragma unroll
            for (int q = 0; q < 4; q++) {
                int pI = t + q * 1024;
                int i = ((pI & ~(j - 1)) << 1) | (pI & (j - 1));
                bool dir = (((base + i) & k) == 0);
                ull a = sk[i], b = sk[i | j];
                if ((a > b) == dir) { sk[i] = b; sk[i | j] = a; }
            }
            __syncthreads();
        }
    #pragma unroll
    for (int r = 0; r < 8; r++) g_keys[base + t + r * 1024] = sk[t + r * 1024];
}

// tail8k with optional fused decorate on the final (k=65536) pass
__global__ __launch_bounds__(1024) void bitonic_smem_tail8k(int k, int final_pass,
                                                            const int* __restrict__ starts,
                                                            const int* __restrict__ ends) {
    extern __shared__ ull sk[];
    int base = blockIdx.x * 8192, t = threadIdx.x;
    #pragma unroll
    for (int r = 0; r < 8; r++) sk[t + r * 1024] = g_keys[base + t + r * 1024];
    __syncthreads();
    for (int j = 4096; j > 0; j >>= 1) {
        #pragma unroll
        for (int q = 0; q < 4; q++) {
            int pI = t + q * 1024;
            int i = ((pI & ~(j - 1)) << 1) | (pI & (j - 1));
            bool dir = (((base + i) & k) == 0);
            ull a = sk[i], b = sk[i | j];
            if ((a > b) == dir) { sk[i] = b; sk[i | j] = a; }
        }
        __syncthreads();
    }
    #pragma unroll
    for (int r = 0; r < 8; r++) {
        int li = t + r * 1024;
        ull key = sk[li];
        g_keys[base + li] = key;
        if (final_pass && base + li < NUM_CAND) {
            int idx = (int)(key & 0xffffffffull);
            g_sorted_se[base + li] = (starts[idx] << 16) | ends[idx];
        }
    }
}

__global__ void bitonic_gstep(int j, int k) {
    int pI = blockIdx.x * blockDim.x + threadIdx.x;
    int i = ((pI & ~(j - 1)) << 1) | (pI & (j - 1));
    bool dir = ((i & k) == 0);
    ull a = g_keys[i], b = g_keys[i | j];
    if ((a > b) == dir) { g_keys[i] = b; g_keys[i | j] = a; }
}

// ---------------- serial greedy NMS + position sort + scalar outputs ----------------
__global__ __launch_bounds__(256) void nms_kernel(const int* __restrict__ starts,
                                                  const int* __restrict__ ends,
                                                  const int* __restrict__ spk,
                                                  float* __restrict__ out) {
    __shared__ int latest[NUM_TOKENS];
    __shared__ int earliest[NUM_TOKENS];
    __shared__ int chunk[2048];
    __shared__ ull akey[NTOP];
    __shared__ int aidx[NTOP];
    __shared__ int s_count;

    int tid = threadIdx.x, lane = tid & 31;
    for (int t = tid; t < NUM_TOKENS; t += 256) { latest[t] = -1; earliest[t] = NUM_TOKENS; }
    if (tid == 0) s_count = 0;
    __syncthreads();

    int count = 0, pos = 0;
    while (pos < NUM_CAND && count < NTOP) {
        int n = min(2048, NUM_CAND - pos);
        for (int t = tid; t < n; t += 256) chunk[t] = g_sorted_se[pos + t];
        __syncthreads();
        if (tid < 32) {
            for (int cI = 0; cI < n && count < NTOP; cI++) {
                int se = chunk[cI];
                int s = se >> 16, e = se & 0xffff;
                int t = s + lane;
                bool act = (lane <= e - s);
                bool c1 = act && (t > s) && (latest[t] > e);
                bool c2 = act && (t < e) && (earliest[t] < s);
                if (__ballot_sync(0xffffffffu, c1 || c2) == 0u) {
                    if (lane == 0) {
                        latest[s] = max(latest[s], e);
                        earliest[e] = min(earliest[e], s);
                        int idx = (int)(g_keys[pos + cI] & 0xffffffffull);
                        aidx[count] = idx;
                        akey[count] = (((ull)(s * (NUM_TOKENS + 1) + e)) << 10) | (unsigned)count;
                    }
                    count++;
                }
                __syncwarp();
            }
            if (lane == 0) s_count = count;
        }
        __syncthreads();
        count = s_count;
        pos += n;
    }
    __syncthreads();
    for (int r = tid; r < NTOP; r += 256)
        if (r >= count) { akey[r] = ~0ull; aidx[r] = 0; }
    __syncthreads();

    for (int k = 2; k <= NTOP; k <<= 1)
        for (int j = k >> 1; j > 0; j >>= 1) {
            int i = ((tid & ~(j - 1)) << 1) | (tid & (j - 1));
            bool dir = ((i & k) == 0);
            ull a = akey[i], b = akey[i | j];
            if ((a > b) == dir) {
                akey[i] = b; akey[i | j] = a;
                int x = aidx[i]; aidx[i] = aidx[i | j]; aidx[i | j] = x;
            }
            __syncthreads();
        }

    int first = aidx[0];
    const size_t base = (size_t)NUM_CAND * SPAN_DIM;
    const size_t emb_off = base + 3 * NTOP;
    const size_t sc_off = emb_off + (size_t)NTOP * SPAN_DIM;
    for (int r = tid; r < NTOP; r += 256) {
        int idx = (r < count) ? aidx[r] : first;
        int s = starts[idx], e = ends[idx];
        out[base + r]            = (float)idx;
        out[base + NTOP + r]     = (float)s;
        out[base + 2 * NTOP + r] = (float)e;
        out[sc_off + r]          = g_scores[idx];
        out[sc_off + NTOP + r]   = (float)spk[s];
        g_pidx[r] = idx;
    }
}

__global__ void gather_emb(float* __restrict__ out) {
    int r = blockIdx.x;
    int idx = g_pidx[r];
    const float* src = out + (size_t)idx * SPAN_DIM;
    float* dst = out + (size_t)NUM_CAND * SPAN_DIM + 3 * NTOP + (size_t)r * SPAN_DIM;
    for (int d = threadIdx.x; d < SPAN_DIM; d += 256) dst[d] = src[d];
}

// ---------------- launch (multi-stream, graph-capturable fork/join) ----------------
extern "C" void kernel_launch(void* const* d_in, const int* in_sizes, int n_in,
                              void* d_out, int out_size) {
    const float* hid    = (const float*)d_in[0];
    const int*   starts = (const int*)  d_in[1];
    const int*   ends   = (const int*)  d_in[2];
    const int*   spk    = (const int*)  d_in[3];
    const float* w_attn = (const float*)d_in[4];
    const float* b_attn = (const float*)d_in[5];
    const float* W1     = (const float*)d_in[6];
    const float* b1     = (const float*)d_in[7];
    const float* W2     = (const float*)d_in[8];
    const float* b2     = (const float*)d_in[9];
    const float* ew     = (const float*)d_in[10];
    const float* ewp    = (const float*)d_in[11];
    const float* Wp1    = (const float*)d_in[12];
    const float* bp1    = (const float*)d_in[13];
    const float* Wp2    = (const float*)d_in[14];
    const float* bp2    = (const float*)d_in[15];
    float* out = (float*)d_out;

    static cudaStream_t sB = 0, sC = 0, sD = 0;
    static cudaEvent_t evRoot = 0, evGL = 0, evGH = 0, evP = 0, evEmb = 0,
                       evScore = 0, evZero = 0;
    if (!sB) {
        cudaStreamCreateWithFlags(&sB, cudaStreamNonBlocking);
        cudaStreamCreateWithFlags(&sC, cudaStreamNonBlocking);
        cudaStreamCreateWithFlags(&sD, cudaStreamNonBlocking);
        cudaEventCreateWithFlags(&evRoot,  cudaEventDisableTiming);
        cudaEventCreateWithFlags(&evGL,    cudaEventDisableTiming);
        cudaEventCreateWithFlags(&evGH,    cudaEventDisableTiming);
        cudaEventCreateWithFlags(&evP,     cudaEventDisableTiming);
        cudaEventCreateWithFlags(&evEmb,   cudaEventDisableTiming);
        cudaEventCreateWithFlags(&evScore, cudaEventDisableTiming);
        cudaEventCreateWithFlags(&evZero,  cudaEventDisableTiming);
        cudaFuncSetAttribute(bitonic_smem_full8k,
                             cudaFuncAttributeMaxDynamicSharedMemorySize, SORT_SMEM);
        cudaFuncSetAttribute(bitonic_smem_tail8k,
                             cudaFuncAttributeMaxDynamicSharedMemorySize, SORT_SMEM);
    }

    cudaEventRecord(evRoot, 0);
    cudaStreamWaitEvent(sB, evRoot, 0);
    cudaStreamWaitEvent(sC, evRoot, 0);
    cudaStreamWaitEvent(sD, evRoot, 0);

    // GEMM halves CONCURRENT on two streams
    sgemm_kernel<<<dim3(24, 8), 256>>>(hid, W1, 0);             // default stream
    cudaEventRecord(evGL, 0);
    sgemm_kernel<<<dim3(24, 8), 256, 0, sD>>>(hid, W1, 1024);   // sD, concurrent
    cudaEventRecord(evGH, sD);

    // setup chain on sB: zero -> presence -> tok_att -> p_pair -> perm -> emb
    zero_kernel<<<256, 256, 0, sB>>>();
    cudaEventRecord(evZero, sB);
    presence_kernel<<<160, 256, 0, sB>>>(starts, ends);
    tok_att_kernel<<<256, 256, 0, sB>>>(hid, w_attn, b_attn);
    p_pair_kernel<<<NPAIR / 8, 256, 0, sB>>>();
    cudaEventRecord(evP, sB);
    scan_kernel<<<1, 1024, 0, sB>>>();
    scatter_kernel<<<160, 256, 0, sB>>>(starts);
    emb_kernel<<<NUM_CAND, 192, 0, sB>>>(hid, starts, ends, ew, out);
    cudaEventRecord(evEmb, sB);

    // tables + score on sC
    tables_kernel<<<20, 256, 0, sC>>>(ew, ewp, W1, Wp1, bp1, Wp2, bp2);
    cudaStreamWaitEvent(sC, evP, 0);
    cudaStreamWaitEvent(sC, evGL, 0);
    cudaStreamWaitEvent(sC, evGH, 0);
    score_pair_kernel<<<NPAIR / 8, 256, 0, sC>>>(b1, W2, b2);
    broadcast_kernel<<<160, 256, 0, sC>>>(starts, ends);
    cudaEventRecord(evScore, sC);

    // join on default stream: sort (final tail fuses decorate) -> nms -> gather
    cudaStreamWaitEvent(0, evScore, 0);
    cudaStreamWaitEvent(0, evZero, 0);
    bitonic_smem_full8k<<<8, 1024, SORT_SMEM>>>();
    for (int k = 16384; k <= 65536; k <<= 1) {
        for (int j = k >> 1; j >= 8192; j >>= 1)
            bitonic_gstep<<<128, 256>>>(j, k);
        bitonic_smem_tail8k<<<8, 1024, SORT_SMEM>>>(k, k == 65536 ? 1 : 0, starts, ends);
    }
    nms_kernel<<<1, 256>>>(starts, ends, spk, out);
    cudaStreamWaitEvent(0, evEmb, 0);
    gather_emb<<<NTOP, 256>>>(out);
}

// round 17
// speedup vs baseline: 1.2542x; 1.0301x over previous
#include <cuda_runtime.h>
#include <stdint.h>

#define NUM_TOKENS 2048
#define HIDDEN     768
#define MAXW       20
#define NUM_CAND   40960
#define UNARY      1024
#define SPAN_DIM   2324     // 3*768 + 20
#define NTOP       512
#define NPAD       65536
#define NPAIR      65536    // s*32 + w

typedef unsigned long long ull;

// ---------------- device scratch ----------------
__device__ float g_P[NUM_TOKENS * 3072];   // [tok][0:1024)=H1a, [1024:2048)=H1b, [2048:3072)=HD
__device__ float g_tok_att[NUM_TOKENS];
__device__ float g_prior[MAXW];
__device__ float g_Cw[MAXW * UNARY];
__device__ float g_pprobs[NPAIR * MAXW];
__device__ float g_pair_score[NPAIR];
__device__ int   g_pair_mark[NPAIR];
__device__ ull   g_keys[NPAD];
__device__ float g_scores[NUM_CAND];
__device__ int   g_sorted_se[NUM_CAND];
__device__ int   g_pidx[NTOP];
__device__ int   g_hist[NUM_TOKENS];
__device__ int   g_base[NUM_TOKENS];
__device__ int   g_perm[NUM_CAND];

// ---------------- f32x2 packed helpers ----------------
__device__ __forceinline__ ull pack2(float lo, float hi) {
    ull r; asm("mov.b64 %0, {%1, %2};" : "=l"(r) : "f"(lo), "f"(hi)); return r;
}
__device__ __forceinline__ ull fma2(ull a, ull b, ull c) {
    ull d; asm("fma.rn.f32x2 %0, %1, %2, %3;" : "=l"(d) : "l"(a), "l"(b), "l"(c)); return d;
}
__device__ __forceinline__ float2 unpack2(ull v) {
    float2 f; asm("mov.b64 {%0, %1}, %2;" : "=f"(f.x), "=f"(f.y) : "l"(v)); return f;
}

// ---------------- combined zero: hist, key padding, pair marks ----------------
__global__ void zero_kernel() {
    int i = blockIdx.x * 256 + threadIdx.x;        // 256*256 = 65536
    if (i < NUM_TOKENS) g_hist[i] = 0;
    if (i < NPAD - NUM_CAND) g_keys[NUM_CAND + i] = ~0ull;
    g_pair_mark[i] = 0;
}

// ---------------- presence + start histogram ----------------
__global__ void presence_kernel(const int* __restrict__ starts,
                                const int* __restrict__ ends) {
    int c = blockIdx.x * 256 + threadIdx.x;
    if (c < NUM_CAND) {
        int s = starts[c];
        g_pair_mark[(s << 5) | (ends[c] - s)] = 1;
        atomicAdd(&g_hist[s], 1);
    }
}

// ---------------- tok_att = hidden @ w_attn + b_attn ----------------
__global__ void tok_att_kernel(const float* __restrict__ hid,
                               const float* __restrict__ w,
                               const float* __restrict__ b) {
    int warp = (blockIdx.x * blockDim.x + threadIdx.x) >> 5;
    int lane = threadIdx.x & 31;
    if (warp >= NUM_TOKENS) return;
    float acc = 0.f;
    for (int k = lane; k < HIDDEN; k += 32)
        acc += hid[(size_t)warp * HIDDEN + k] * w[k];
    #pragma unroll
    for (int o = 16; o; o >>= 1) acc += __shfl_down_sync(0xffffffffu, acc, o);
    if (lane == 0) g_tok_att[warp] = acc + b[0];
}

// ---------------- width tables ----------------
__global__ void tables_kernel(const float* __restrict__ ew,
                              const float* __restrict__ ewp,
                              const float* __restrict__ W1,
                              const float* __restrict__ Wp1,
                              const float* __restrict__ bp1,
                              const float* __restrict__ Wp2,
                              const float* __restrict__ bp2) {
    int w = blockIdx.x;
    int tid = threadIdx.x;
    __shared__ float red[256];
    float local = 0.f;
    for (int u = tid; u < UNARY; u += 256) {
        float cw = 0.f, hp = 0.f;
        #pragma unroll
        for (int f = 0; f < MAXW; f++) {
            cw += ew [w * MAXW + f] * W1 [(size_t)(1536 + f) * UNARY + u];
            hp += ewp[w * MAXW + f] * Wp1[(size_t)f * UNARY + u];
        }
        g_Cw[w * UNARY + u] = cw;
        hp += bp1[u];
        hp = fmaxf(hp, 0.f);
        local += hp * Wp2[u];
    }
    red[tid] = local;
    __syncthreads();
    for (int s = 128; s; s >>= 1) {
        if (tid < s) red[tid] += red[tid + s];
        __syncthreads();
    }
    if (tid == 0) g_prior[w] = red[0] + bp2[0];
}

// ---------------- counting-sort permutation by start ----------------
__global__ __launch_bounds__(1024) void scan_kernel() {
    __shared__ int a[2048], b[2048];
    int t = threadIdx.x;
    a[t] = g_hist[t]; a[t + 1024] = g_hist[t + 1024];
    __syncthreads();
    int* src = a; int* dst = b;
    for (int off = 1; off < 2048; off <<= 1) {
        #pragma unroll
        for (int q = 0; q < 2; q++) {
            int i = t + q * 1024;
            dst[i] = src[i] + (i >= off ? src[i - off] : 0);
        }
        __syncthreads();
        int* tmp = src; src = dst; dst = tmp;
    }
    g_base[t]        = t ? src[t - 1] : 0;
    g_base[t + 1024] = src[t + 1023];
}
__global__ void scatter_kernel(const int* __restrict__ starts) {
    int c = blockIdx.x * 256 + threadIdx.x;
    if (c < NUM_CAND) {
        int pos = atomicAdd(&g_base[starts[c]], 1);
        g_perm[pos] = c;
    }
}

// ---------------- SGEMM half (R8 quadrant tile, conflict-free LDS, f32x2) ----------------
#define BM 128
#define BN 128
#define BK 16
__global__ __launch_bounds__(256, 2) void sgemm_kernel(const float* __restrict__ A,
                                                       const float* __restrict__ W1,
                                                       int m0) {
    __shared__ float As[2][BK][BM];
    __shared__ float Bs[2][BK][BN];
    int bm = m0 + blockIdx.y * BM, bn = blockIdx.x * BN;
    int tid = threadIdx.x;
    int tr = tid >> 4, tc = tid & 15;

    ull acc[2][4][4];
    #pragma unroll
    for (int q = 0; q < 2; q++)
        #pragma unroll
        for (int i = 0; i < 4; i++)
            #pragma unroll
            for (int p = 0; p < 4; p++) acc[q][i][p] = 0ull;

    int a_row = tid >> 2;
    int a_col = (tid & 3) << 2;
    int b_k   = tid >> 5;
    int b_n   = (tid & 31) << 2;

    int n_global = bn + b_n;
    int seg_off = (n_global < 1024) ? 0 : (n_global < 2048 ? 768 : 1556);
    int col = n_global & 1023;

    float4 ra0, ra1, rb0, rb1;
    ra0 = *reinterpret_cast<const float4*>(&A[(size_t)(bm + a_row) * HIDDEN + a_col]);
    ra1 = *reinterpret_cast<const float4*>(&A[(size_t)(bm + a_row + 64) * HIDDEN + a_col]);
    rb0 = *reinterpret_cast<const float4*>(&W1[(size_t)(seg_off + b_k) * UNARY + col]);
    rb1 = *reinterpret_cast<const float4*>(&W1[(size_t)(seg_off + b_k + 8) * UNARY + col]);
    {
        As[0][a_col + 0][a_row] = ra0.x; As[0][a_col + 1][a_row] = ra0.y;
        As[0][a_col + 2][a_row] = ra0.z; As[0][a_col + 3][a_row] = ra0.w;
        As[0][a_col + 0][a_row + 64] = ra1.x; As[0][a_col + 1][a_row + 64] = ra1.y;
        As[0][a_col + 2][a_row + 64] = ra1.z; As[0][a_col + 3][a_row + 64] = ra1.w;
        *reinterpret_cast<float4*>(&Bs[0][b_k][b_n]) = rb0;
        *reinterpret_cast<float4*>(&Bs[0][b_k + 8][b_n]) = rb1;
    }
    __syncthreads();

    int buf = 0;
    for (int kt = 0; kt < HIDDEN; kt += BK) {
        bool more = (kt + BK) < HIDDEN;
        if (more) {
            int kn = kt + BK;
            ra0 = *reinterpret_cast<const float4*>(&A[(size_t)(bm + a_row) * HIDDEN + kn + a_col]);
            ra1 = *reinterpret_cast<const float4*>(&A[(size_t)(bm + a_row + 64) * HIDDEN + kn + a_col]);
            rb0 = *reinterpret_cast<const float4*>(&W1[(size_t)(seg_off + kn + b_k) * UNARY + col]);
            rb1 = *reinterpret_cast<const float4*>(&W1[(size_t)(seg_off + kn + b_k + 8) * UNARY + col]);
        }
        #pragma unroll
        for (int kk = 0; kk < BK; kk++) {
            float4 a0 = *reinterpret_cast<const float4*>(&As[buf][kk][tr * 4]);
            float4 a1 = *reinterpret_cast<const float4*>(&As[buf][kk][64 + tr * 4]);
            ulonglong2 b0 = *reinterpret_cast<const ulonglong2*>(&Bs[buf][kk][tc * 4]);
            ulonglong2 b1v = *reinterpret_cast<const ulonglong2*>(&Bs[buf][kk][64 + tc * 4]);
            ull ap[8];
            ap[0] = pack2(a0.x, a0.x); ap[1] = pack2(a0.y, a0.y);
            ap[2] = pack2(a0.z, a0.z); ap[3] = pack2(a0.w, a0.w);
            ap[4] = pack2(a1.x, a1.x); ap[5] = pack2(a1.y, a1.y);
            ap[6] = pack2(a1.z, a1.z); ap[7] = pack2(a1.w, a1.w);
            #pragma unroll
            for (int q = 0; q < 2; q++)
                #pragma unroll
                for (int i = 0; i < 4; i++) {
                    ull aa = ap[q * 4 + i];
                    acc[q][i][0] = fma2(aa, b0.x,  acc[q][i][0]);
                    acc[q][i][1] = fma2(aa, b0.y,  acc[q][i][1]);
                    acc[q][i][2] = fma2(aa, b1v.x, acc[q][i][2]);
                    acc[q][i][3] = fma2(aa, b1v.y, acc[q][i][3]);
                }
        }
        if (more) {
            int nb = buf ^ 1;
            As[nb][a_col + 0][a_row] = ra0.x; As[nb][a_col + 1][a_row] = ra0.y;
            As[nb][a_col + 2][a_row] = ra0.z; As[nb][a_col + 3][a_row] = ra0.w;
            As[nb][a_col + 0][a_row + 64] = ra1.x; As[nb][a_col + 1][a_row + 64] = ra1.y;
            As[nb][a_col + 2][a_row + 64] = ra1.z; As[nb][a_col + 3][a_row + 64] = ra1.w;
            *reinterpret_cast<float4*>(&Bs[nb][b_k][b_n]) = rb0;
            *reinterpret_cast<float4*>(&Bs[nb][b_k + 8][b_n]) = rb1;
            __syncthreads();
            buf = nb;
        }
    }
    #pragma unroll
    for (int q = 0; q < 2; q++)
        #pragma unroll
        for (int i = 0; i < 4; i++) {
            int row = bm + q * 64 + tr * 4 + i;
            float2 v0 = unpack2(acc[q][i][0]), v1 = unpack2(acc[q][i][1]);
            float2 v2 = unpack2(acc[q][i][2]), v3 = unpack2(acc[q][i][3]);
            float4 w0 = make_float4(v0.x, v0.y, v1.x, v1.y);
            float4 w1 = make_float4(v2.x, v2.y, v3.x, v3.y);
            *reinterpret_cast<float4*>(&g_P[(size_t)row * 3072 + bn + tc * 4])      = w0;
            *reinterpret_cast<float4*>(&g_P[(size_t)row * 3072 + bn + 64 + tc * 4]) = w1;
        }
}

// ---------------- softmax probs: one warp per PRESENT pair (sparse, ordered) ----------------
__global__ __launch_bounds__(256) void p_pair_kernel() {
    int pid = blockIdx.x * 8 + (threadIdx.x >> 5);
    int lane = threadIdx.x & 31;
    if (pid >= NPAIR) return;
    if (!g_pair_mark[pid]) return;
    int s = pid >> 5, wi = pid & 31;
    float l = (lane <= wi) ? g_tok_att[s + lane] : __int_as_float(0xff800000);
    float m = l;
    #pragma unroll
    for (int o = 16; o; o >>= 1) m = fmaxf(m, __shfl_xor_sync(0xffffffffu, m, o));
    float ex = (lane <= wi) ? expf(l - m) : 0.f;
    float sm = ex;
    #pragma unroll
    for (int o = 16; o; o >>= 1) sm += __shfl_xor_sync(0xffffffffu, sm, o);
    if (lane < MAXW) g_pprobs[pid * MAXW + lane] = (lane <= wi) ? (ex / sm) : 0.f;
}

// ---------------- span_emb rows (perm order, streaming stores) ----------------
__global__ __launch_bounds__(192) void emb_kernel(const float* __restrict__ hid,
                                                  const int* __restrict__ starts,
                                                  const int* __restrict__ ends,
                                                  const float* __restrict__ ew,
                                                  float* __restrict__ out) {
    int c = g_perm[blockIdx.x];
    int tid = threadIdx.x;
    int s = starts[c], e = ends[c];
    int wi = e - s;
    int pid = (s << 5) | wi;

    __shared__ float p[MAXW];
    if (tid < MAXW) p[tid] = g_pprobs[pid * MAXW + tid];
    __syncthreads();

    float4* row4 = reinterpret_cast<float4*>(out + (size_t)c * SPAN_DIM);
    const float4* hid4 = reinterpret_cast<const float4*>(hid);

    float4 acc = make_float4(0.f, 0.f, 0.f, 0.f);
    for (int i = 0; i <= wi; i++) {
        float4 v = hid4[(size_t)(s + i) * 192 + tid];
        if (i == 0)  __stcs(&row4[tid], v);
        if (i == wi) __stcs(&row4[192 + tid], v);
        float pi = p[i];
        acc.x += pi * v.x; acc.y += pi * v.y; acc.z += pi * v.z; acc.w += pi * v.w;
    }
    __stcs(&row4[389 + tid], acc);
    if (tid < 5) {
        float4 w = reinterpret_cast<const float4*>(ew)[wi * 5 + tid];
        __stcs(&row4[384 + tid], w);
    }
}

// ---------------- score: one warp per PRESENT pair; forced 4 CTAs/SM ----------------
__global__ __launch_bounds__(256, 4) void score_pair_kernel(const float* __restrict__ b1,
                                                            const float* __restrict__ W2,
                                                            const float* __restrict__ b2v) {
    int pid = blockIdx.x * 8 + (threadIdx.x >> 5);
    int lane = threadIdx.x & 31;
    if (pid >= NPAIR) return;
    if (!g_pair_mark[pid]) return;
    int s = pid >> 5, wi = pid & 31;
    int e = s + wi;

    float pv = (lane <= wi) ? g_pprobs[pid * MAXW + lane] : 0.f;

    const float4* pa  = reinterpret_cast<const float4*>(&g_P[(size_t)s * 3072]);
    const float4* pb  = reinterpret_cast<const float4*>(&g_P[(size_t)e * 3072 + 1024]);
    const float4* pcw = reinterpret_cast<const float4*>(&g_Cw[wi * UNARY]);
    const float4* pb1 = reinterpret_cast<const float4*>(b1);

    float4 acc[8];
    #pragma unroll
    for (int j = 0; j < 8; j++) {
        int idx = j * 32 + lane;
        float4 a = pa[idx], b = pb[idx], cw = pcw[idx], bb = pb1[idx];
        acc[j].x = a.x + b.x + cw.x + bb.x;
        acc[j].y = a.y + b.y + cw.y + bb.y;
        acc[j].z = a.z + b.z + cw.z + bb.z;
        acc[j].w = a.w + b.w + cw.w + bb.w;
    }
    for (int i = 0; i <= wi; i++) {
        float pi = __shfl_sync(0xffffffffu, pv, i);
        const float4* hd = reinterpret_cast<const float4*>(&g_P[(size_t)(s + i) * 3072 + 2048]);
        #pragma unroll
        for (int j = 0; j < 8; j++) {
            float4 v = hd[j * 32 + lane];
            acc[j].x += pi * v.x; acc[j].y += pi * v.y;
            acc[j].z += pi * v.z; acc[j].w += pi * v.w;
        }
    }
    const float4* W2_4 = reinterpret_cast<const float4*>(W2);
    float local = 0.f;
    #pragma unroll
    for (int j = 0; j < 8; j++) {
        float4 w = W2_4[j * 32 + lane];
        local += fmaxf(acc[j].x, 0.f) * w.x + fmaxf(acc[j].y, 0.f) * w.y
               + fmaxf(acc[j].z, 0.f) * w.z + fmaxf(acc[j].w, 0.f) * w.w;
    }
    #pragma unroll
    for (int o = 16; o; o >>= 1) local += __shfl_xor_sync(0xffffffffu, local, o);
    if (lane == 0) g_pair_score[pid] = local + b2v[0] + g_prior[wi];
}

// ---------------- broadcast pair score to candidates + build keys ----------------
__global__ void broadcast_kernel(const int* __restrict__ starts,
                                 const int* __restrict__ ends) {
    int c = blockIdx.x * 256 + threadIdx.x;
    if (c >= NUM_CAND) return;
    int s = starts[c];
    float sc = g_pair_score[(s << 5) | (ends[c] - s)];
    g_scores[c] = sc;
    unsigned u = __float_as_uint(sc);
    u = (u & 0x80000000u) ? ~u : (u | 0x80000000u);
    g_keys[c] = ((ull)(~u) << 32) | (unsigned)c;
}

// ---------------- bitonic sort, 8192-element smem chunks ----------------
#define SORT_SMEM (8192 * 8)
__global__ __launch_bounds__(1024) void bitonic_smem_full8k() {
    extern __shared__ ull sk[];
    int base = blockIdx.x * 8192, t = threadIdx.x;
    #pragma unroll
    for (int r = 0; r < 8; r++) sk[t + r * 1024] = g_keys[base + t + r * 1024];
    __syncthreads();
    for (int k = 2; k <= 8192; k <<= 1)
        for (int j = k >> 1; j > 0; j >>= 1) {
            #pragma unroll
            for (int q = 0; q < 4; q++) {
                int pI = t + q * 1024;
                int i = ((pI & ~(j - 1)) << 1) | (pI & (j - 1));
                bool dir = (((base + i) & k) == 0);
                ull a = sk[i], b = sk[i | j];
                if ((a > b) == dir) { sk[i] = b; sk[i | j] = a; }
            }
            __syncthreads();
        }
    #pragma unroll
    for (int r = 0; r < 8; r++) g_keys[base + t + r * 1024] = sk[t + r * 1024];
}

// tail8k with optional fused decorate on the final (k=65536) pass
__global__ __launch_bounds__(1024) void bitonic_smem_tail8k(int k, int final_pass,
                                                            const int* __restrict__ starts,
                                                            const int* __restrict__ ends) {
    extern __shared__ ull sk[];
    int base = blockIdx.x * 8192, t = threadIdx.x;
    #pragma unroll
    for (int r = 0; r < 8; r++) sk[t + r * 1024] = g_keys[base + t + r * 1024];
    __syncthreads();
    for (int j = 4096; j > 0; j >>= 1) {
        #pragma unroll
        for (int q = 0; q < 4; q++) {
            int pI = t + q * 1024;
            int i = ((pI & ~(j - 1)) << 1) | (pI & (j - 1));
            bool dir = (((base + i) & k) == 0);
            ull a = sk[i], b = sk[i | j];
            if ((a > b) == dir) { sk[i] = b; sk[i | j] = a; }
        }
        __syncthreads();
    }
    #pragma unroll
    for (int r = 0; r < 8; r++) {
        int li = t + r * 1024;
        ull key = sk[li];
        g_keys[base + li] = key;
        if (final_pass && base + li < NUM_CAND) {
            int idx = (int)(key & 0xffffffffull);
            g_sorted_se[base + li] = (starts[idx] << 16) | ends[idx];
        }
    }
}

__global__ void bitonic_gstep(int j, int k) {
    int pI = blockIdx.x * blockDim.x + threadIdx.x;
    int i = ((pI & ~(j - 1)) << 1) | (pI & (j - 1));
    bool dir = ((i & k) == 0);
    ull a = g_keys[i], b = g_keys[i | j];
    if ((a > b) == dir) { g_keys[i] = b; g_keys[i | j] = a; }
}

// ---------------- serial greedy NMS + position sort + scalar outputs ----------------
__global__ __launch_bounds__(256) void nms_kernel(const int* __restrict__ starts,
                                                  const int* __restrict__ ends,
                                                  const int* __restrict__ spk,
                                                  float* __restrict__ out) {
    __shared__ int latest[NUM_TOKENS];
    __shared__ int earliest[NUM_TOKENS];
    __shared__ int chunk[2048];
    __shared__ ull akey[NTOP];
    __shared__ int aidx[NTOP];
    __shared__ int s_count;

    int tid = threadIdx.x, lane = tid & 31;
    for (int t = tid; t < NUM_TOKENS; t += 256) { latest[t] = -1; earliest[t] = NUM_TOKENS; }
    if (tid == 0) s_count = 0;
    __syncthreads();

    int count = 0, pos = 0;
    while (pos < NUM_CAND && count < NTOP) {
        int n = min(2048, NUM_CAND - pos);
        for (int t = tid; t < n; t += 256) chunk[t] = g_sorted_se[pos + t];
        __syncthreads();
        if (tid < 32) {
            for (int cI = 0; cI < n && count < NTOP; cI++) {
                int se = chunk[cI];
                int s = se >> 16, e = se & 0xffff;
                int t = s + lane;
                bool act = (lane <= e - s);
                bool c1 = act && (t > s) && (latest[t] > e);
                bool c2 = act && (t < e) && (earliest[t] < s);
                if (__ballot_sync(0xffffffffu, c1 || c2) == 0u) {
                    if (lane == 0) {
                        latest[s] = max(latest[s], e);
                        earliest[e] = min(earliest[e], s);
                        int idx = (int)(g_keys[pos + cI] & 0xffffffffull);
                        aidx[count] = idx;
                        akey[count] = (((ull)(s * (NUM_TOKENS + 1) + e)) << 10) | (unsigned)count;
                    }
                    count++;
                }
                __syncwarp();
            }
            if (lane == 0) s_count = count;
        }
        __syncthreads();
        count = s_count;
        pos += n;
    }
    __syncthreads();
    for (int r = tid; r < NTOP; r += 256)
        if (r >= count) { akey[r] = ~0ull; aidx[r] = 0; }
    __syncthreads();

    for (int k = 2; k <= NTOP; k <<= 1)
        for (int j = k >> 1; j > 0; j >>= 1) {
            int i = ((tid & ~(j - 1)) << 1) | (tid & (j - 1));
            bool dir = ((i & k) == 0);
            ull a = akey[i], b = akey[i | j];
            if ((a > b) == dir) {
                akey[i] = b; akey[i | j] = a;
                int x = aidx[i]; aidx[i] = aidx[i | j]; aidx[i | j] = x;
            }
            __syncthreads();
        }

    int first = aidx[0];
    const size_t base = (size_t)NUM_CAND * SPAN_DIM;
    const size_t emb_off = base + 3 * NTOP;
    const size_t sc_off = emb_off + (size_t)NTOP * SPAN_DIM;
    for (int r = tid; r < NTOP; r += 256) {
        int idx = (r < count) ? aidx[r] : first;
        int s = starts[idx], e = ends[idx];
        out[base + r]            = (float)idx;
        out[base + NTOP + r]     = (float)s;
        out[base + 2 * NTOP + r] = (float)e;
        out[sc_off + r]          = g_scores[idx];
        out[sc_off + NTOP + r]   = (float)spk[s];
        g_pidx[r] = idx;
    }
}

__global__ void gather_emb(float* __restrict__ out) {
    int r = blockIdx.x;
    int idx = g_pidx[r];
    const float* src = out + (size_t)idx * SPAN_DIM;
    float* dst = out + (size_t)NUM_CAND * SPAN_DIM + 3 * NTOP + (size_t)r * SPAN_DIM;
    for (int d = threadIdx.x; d < SPAN_DIM; d += 256) dst[d] = src[d];
}

// ---------------- launch (multi-stream, graph-capturable fork/join) ----------------
extern "C" void kernel_launch(void* const* d_in, const int* in_sizes, int n_in,
                              void* d_out, int out_size) {
    const float* hid    = (const float*)d_in[0];
    const int*   starts = (const int*)  d_in[1];
    const int*   ends   = (const int*)  d_in[2];
    const int*   spk    = (const int*)  d_in[3];
    const float* w_attn = (const float*)d_in[4];
    const float* b_attn = (const float*)d_in[5];
    const float* W1     = (const float*)d_in[6];
    const float* b1     = (const float*)d_in[7];
    const float* W2     = (const float*)d_in[8];
    const float* b2     = (const float*)d_in[9];
    const float* ew     = (const float*)d_in[10];
    const float* ewp    = (const float*)d_in[11];
    const float* Wp1    = (const float*)d_in[12];
    const float* bp1    = (const float*)d_in[13];
    const float* Wp2    = (const float*)d_in[14];
    const float* bp2    = (const float*)d_in[15];
    float* out = (float*)d_out;

    static cudaStream_t sB = 0, sC = 0, sD = 0;
    static cudaEvent_t evRoot = 0, evGL = 0, evGH = 0, evP = 0, evEmb = 0,
                       evScore = 0, evZero = 0;
    if (!sB) {
        cudaStreamCreateWithFlags(&sB, cudaStreamNonBlocking);
        cudaStreamCreateWithFlags(&sC, cudaStreamNonBlocking);
        cudaStreamCreateWithFlags(&sD, cudaStreamNonBlocking);
        cudaEventCreateWithFlags(&evRoot,  cudaEventDisableTiming);
        cudaEventCreateWithFlags(&evGL,    cudaEventDisableTiming);
        cudaEventCreateWithFlags(&evGH,    cudaEventDisableTiming);
        cudaEventCreateWithFlags(&evP,     cudaEventDisableTiming);
        cudaEventCreateWithFlags(&evEmb,   cudaEventDisableTiming);
        cudaEventCreateWithFlags(&evScore, cudaEventDisableTiming);
        cudaEventCreateWithFlags(&evZero,  cudaEventDisableTiming);
        cudaFuncSetAttribute(bitonic_smem_full8k,
                             cudaFuncAttributeMaxDynamicSharedMemorySize, SORT_SMEM);
        cudaFuncSetAttribute(bitonic_smem_tail8k,
                             cudaFuncAttributeMaxDynamicSharedMemorySize, SORT_SMEM);
    }

    cudaEventRecord(evRoot, 0);
    cudaStreamWaitEvent(sB, evRoot, 0);
    cudaStreamWaitEvent(sC, evRoot, 0);
    cudaStreamWaitEvent(sD, evRoot, 0);

    // GEMM halves CONCURRENT on two streams
    sgemm_kernel<<<dim3(24, 8), 256>>>(hid, W1, 0);             // default stream
    cudaEventRecord(evGL, 0);
    sgemm_kernel<<<dim3(24, 8), 256, 0, sD>>>(hid, W1, 1024);   // sD, concurrent
    cudaEventRecord(evGH, sD);

    // setup chain on sB: zero -> presence -> tok_att -> p_pair -> perm -> emb
    zero_kernel<<<256, 256, 0, sB>>>();
    cudaEventRecord(evZero, sB);
    presence_kernel<<<160, 256, 0, sB>>>(starts, ends);
    tok_att_kernel<<<256, 256, 0, sB>>>(hid, w_attn, b_attn);
    p_pair_kernel<<<NPAIR / 8, 256, 0, sB>>>();
    cudaEventRecord(evP, sB);
    scan_kernel<<<1, 1024, 0, sB>>>();
    scatter_kernel<<<160, 256, 0, sB>>>(starts);
    emb_kernel<<<NUM_CAND, 192, 0, sB>>>(hid, starts, ends, ew, out);
    cudaEventRecord(evEmb, sB);

    // tables + score on sC
    tables_kernel<<<20, 256, 0, sC>>>(ew, ewp, W1, Wp1, bp1, Wp2, bp2);
    cudaStreamWaitEvent(sC, evP, 0);
    cudaStreamWaitEvent(sC, evGL, 0);
    cudaStreamWaitEvent(sC, evGH, 0);
    score_pair_kernel<<<NPAIR / 8, 256, 0, sC>>>(b1, W2, b2);
    broadcast_kernel<<<160, 256, 0, sC>>>(starts, ends);
    cudaEventRecord(evScore, sC);

    // join on default stream: sort (final tail fuses decorate) -> nms -> gather
    cudaStreamWaitEvent(0, evScore, 0);
    cudaStreamWaitEvent(0, evZero, 0);
    bitonic_smem_full8k<<<8, 1024, SORT_SMEM>>>();
    for (int k = 16384; k <= 65536; k <<= 1) {
        for (int j = k >> 1; j >= 8192; j >>= 1)
            bitonic_gstep<<<128, 256>>>(j, k);
        bitonic_smem_tail8k<<<8, 1024, SORT_SMEM>>>(k, k == 65536 ? 1 : 0, starts, ends);
    }
    nms_kernel<<<1, 256>>>(starts, ends, spk, out);
    cudaStreamWaitEvent(0, evEmb, 0);
    gather_emb<<<NTOP, 256>>>(out);
}